// round 12
// baseline (speedup 1.0000x reference)
#include <cuda_runtime.h>
#include <math.h>
#include <stdint.h>

// Problem constants
#define Bn  4
#define Sn  2048
#define Dn  1024
#define Hn  16
#define HDn 64
#define TEn 64
#define Mn  (Bn * Sn)   // 8192

// ---------------------------------------------------------------------------
// Scratch
// ---------------------------------------------------------------------------
__device__ float g_q[Bn * Hn * Sn * HDn];      // [B,H,S,HD]
__device__ float g_k[Bn * Hn * Sn * HDn];
__device__ float g_v[Bn * Hn * Sn * HDn];
__device__ float g_attn[Bn * Sn * Dn];         // [B,S,D]
__device__ float g_bias[Bn * Hn];

// ---------------------------------------------------------------------------
// PTX helpers
// ---------------------------------------------------------------------------
__device__ __forceinline__ uint32_t f2tf32(float f) {
    uint32_t u;
    asm("cvt.rna.tf32.f32 %0, %1;" : "=r"(u) : "f"(f));
    return u;
}
__device__ __forceinline__ uint32_t u2tf32(uint32_t x) {
    uint32_t y;
    asm("cvt.rna.tf32.f32 %0, %1;" : "=r"(y) : "f"(__uint_as_float(x)));
    return y;
}

__device__ __forceinline__ void mma_tf32(float c[4],
                                         uint32_t a0, uint32_t a1, uint32_t a2, uint32_t a3,
                                         uint32_t b0, uint32_t b1) {
    asm volatile(
        "mma.sync.aligned.m16n8k8.row.col.f32.tf32.tf32.f32 "
        "{%0,%1,%2,%3}, {%4,%5,%6,%7}, {%8,%9}, {%0,%1,%2,%3};"
        : "+f"(c[0]), "+f"(c[1]), "+f"(c[2]), "+f"(c[3])
        : "r"(a0), "r"(a1), "r"(a2), "r"(a3), "r"(b0), "r"(b1));
}

__device__ __forceinline__ void ldm_x4(uint32_t r[4], const float* p) {
    uint32_t addr = (uint32_t)__cvta_generic_to_shared(p);
    asm volatile("ldmatrix.sync.aligned.m8n8.x4.shared.b16 {%0,%1,%2,%3}, [%4];"
                 : "=r"(r[0]), "=r"(r[1]), "=r"(r[2]), "=r"(r[3])
                 : "r"(addr));
}

__device__ __forceinline__ void cp16(float* dst, const float* src) {
    uint32_t d = (uint32_t)__cvta_generic_to_shared(dst);
    asm volatile("cp.async.cg.shared.global [%0], [%1], 16;" :: "r"(d), "l"(src));
}
__device__ __forceinline__ void cp_commit() {
    asm volatile("cp.async.commit_group;" ::: "memory");
}
template<int N>
__device__ __forceinline__ void cp_wait() {
    asm volatile("cp.async.wait_group %0;" :: "n"(N) : "memory");
}

// ---------------------------------------------------------------------------
// Kernel 1: task bias  (B,TE) @ (TE,H) + bt -> (B,H)
// ---------------------------------------------------------------------------
__global__ void task_bias_kernel(const float* __restrict__ te,
                                 const float* __restrict__ Wt,
                                 const float* __restrict__ bt) {
    int t = threadIdx.x;
    if (t < Bn * Hn) {
        int b = t / Hn, h = t % Hn;
        float acc = bt[h];
        #pragma unroll 8
        for (int i = 0; i < TEn; i++) acc += te[b * TEn + i] * Wt[i * Hn + h];
        g_bias[t] = acc;
    }
}

// ---------------------------------------------------------------------------
// tf32 tensor-core GEMM, cp.async double-buffered.
// BM=128, BN=128, BK=32, 256 threads = 8 warps (4M x 2N), warp tile 32x64.
// Raw fp32 in smem; tf32 conversion happens on register fragments.
// ---------------------------------------------------------------------------
#define AS_ST 36     // A smem stride (floats); 144B rows, 16B aligned
#define BS_ST 136    // B smem stride; 136 % 32 == 8 -> conflict-free B-frag LDS

template<int SCATTER>
__device__ __forceinline__ void gemm_tf32_body(
    const float* __restrict__ A, const float* __restrict__ W,
    const float* __restrict__ bias, float* __restrict__ out)
{
    __shared__ float As[2][128 * AS_ST];
    __shared__ float Bs[2][32 * BS_ST];

    const int tid  = threadIdx.x;
    const int lane = tid & 31;
    const int warp = tid >> 5;
    const int wm   = warp & 3;
    const int wn   = warp >> 2;
    const int m0   = blockIdx.y * 128;
    const int n0   = blockIdx.x * 128;

    const int arow = (lane < 16) ? lane : lane - 16;
    const int acol = (lane < 16) ? 0 : 4;
    const int lk   = lane & 3;
    const int ln   = lane >> 2;

    float acc[2][8][4] = {};

    const int NK = Dn / 32;   // 32 k-steps

    auto issue = [&](int kk, int s) {
        #pragma unroll
        for (int i = 0; i < 4; i++) {
            int lin = tid + i * 256;
            int r = lin >> 3, c4 = (lin & 7) << 2;
            cp16(&As[s][r * AS_ST + c4], &A[(size_t)(m0 + r) * Dn + kk + c4]);
        }
        #pragma unroll
        for (int i = 0; i < 4; i++) {
            int lin = tid + i * 256;
            int r = lin >> 5, c4 = (lin & 31) << 2;
            cp16(&Bs[s][r * BS_ST + c4], &W[(size_t)(kk + r) * Dn + n0 + c4]);
        }
        cp_commit();
    };

    issue(0, 0);
    issue(32, 1);

    for (int kstep = 0; kstep < NK; kstep++) {
        const int s = kstep & 1;
        if (kstep + 1 < NK) cp_wait<1>(); else cp_wait<0>();
        __syncthreads();

        #pragma unroll
        for (int ks = 0; ks < 4; ks++) {
            const int k0 = ks * 8;
            uint32_t af[2][4];
            #pragma unroll
            for (int mi = 0; mi < 2; mi++) {
                ldm_x4(af[mi], &As[s][(wm * 32 + mi * 16 + arow) * AS_ST + k0 + acol]);
                #pragma unroll
                for (int j = 0; j < 4; j++) af[mi][j] = u2tf32(af[mi][j]);
            }
            uint32_t bf0[8], bf1[8];
            #pragma unroll
            for (int ni = 0; ni < 8; ni++) {
                int n = wn * 64 + ni * 8 + ln;
                bf0[ni] = f2tf32(Bs[s][(k0 + lk)     * BS_ST + n]);
                bf1[ni] = f2tf32(Bs[s][(k0 + 4 + lk) * BS_ST + n]);
            }
            #pragma unroll
            for (int mi = 0; mi < 2; mi++)
                #pragma unroll
                for (int ni = 0; ni < 8; ni++)
                    mma_tf32(acc[mi][ni], af[mi][0], af[mi][1], af[mi][2], af[mi][3],
                             bf0[ni], bf1[ni]);
        }
        __syncthreads();
        if (kstep + 2 < NK) issue((kstep + 2) * 32, s);
    }

    // epilogue
    #pragma unroll
    for (int mi = 0; mi < 2; mi++) {
        #pragma unroll
        for (int ni = 0; ni < 8; ni++) {
            int n = n0 + wn * 64 + ni * 8 + lk * 2;
            float bb0 = bias[n], bb1 = bias[n + 1];
            #pragma unroll
            for (int rr = 0; rr < 2; rr++) {
                int m = m0 + wm * 32 + mi * 16 + ln + rr * 8;
                float2 o;
                o.x = acc[mi][ni][rr * 2 + 0] + bb0;
                o.y = acc[mi][ni][rr * 2 + 1] + bb1;
                if (SCATTER) {
                    int b = m >> 11, sI = m & (Sn - 1);
                    int h = n >> 6, hd = n & 63;
                    *(float2*)&out[((size_t)(b * Hn + h) * Sn + sI) * HDn + hd] = o;
                } else {
                    *(float2*)&out[(size_t)m * Dn + n] = o;
                }
            }
        }
    }
}

__global__ __launch_bounds__(256, 2)
void qkv_gemm_tc_kernel(const float* __restrict__ x,
                        const float* __restrict__ Wq, const float* __restrict__ bq,
                        const float* __restrict__ Wk, const float* __restrict__ bk,
                        const float* __restrict__ Wv, const float* __restrict__ bv) {
    const float* W; const float* bias; float* out;
    if (blockIdx.z == 0)      { W = Wq; bias = bq; out = g_q; }
    else if (blockIdx.z == 1) { W = Wk; bias = bk; out = g_k; }
    else                      { W = Wv; bias = bv; out = g_v; }
    gemm_tf32_body<1>(x, W, bias, out);
}

__global__ __launch_bounds__(256, 2)
void out_gemm_tc_kernel(const float* __restrict__ Wo,
                        const float* __restrict__ bo,
                        float* __restrict__ out) {
    gemm_tf32_body<0>(g_attn, Wo, bo, out);
}

// ---------------------------------------------------------------------------
// Kernel 3: tensor-core flash attention, 128 q-rows / 8 warps per block,
// cp.async double-buffered K/V tiles (64 keys each).
// Smem: Ps 128x68 (holds raw Q during prologue, then tf32 P),
//       Ks[2] 64x68 raw fp32, Vs[2] 64x72 raw fp32.
// tf32 conversion on register fragments.
// ---------------------------------------------------------------------------
#define QP_ST 68
#define KS_ST 68
#define VS_ST 72
#define ATTN_SMEM_FLOATS (128 * QP_ST + 2 * 64 * KS_ST + 2 * 64 * VS_ST)
#define ATTN_SMEM_BYTES  (ATTN_SMEM_FLOATS * 4)

__global__ __launch_bounds__(256, 1)
void attn_tc_kernel(const int* __restrict__ mask) {
    extern __shared__ float sm[];
    float* Ps = sm;                                 // 128*68
    float* Ks = sm + 128 * QP_ST;                   // 2 * 64*68
    float* Vs = Ks + 2 * 64 * KS_ST;                // 2 * 64*72
    __shared__ int maskS[2][64];

    const int tid  = threadIdx.x;
    const int lane = tid & 31;
    const int warp = tid >> 5;                      // 0..7
    const int q0   = blockIdx.x * 128;
    const int h    = blockIdx.y;
    const int b    = blockIdx.z;

    const float* qb = g_q + ((size_t)(b * Hn + h) * Sn + q0) * HDn;
    const float* kb = g_k + ((size_t)(b * Hn + h) * Sn) * HDn;
    const float* vb = g_v + ((size_t)(b * Hn + h) * Sn) * HDn;
    const float bias  = g_bias[b * Hn + h];
    const float scale = 0.125f;

    const int arow = (lane < 16) ? lane : lane - 16;
    const int acol = (lane < 16) ? 0 : 4;
    const int lk   = lane & 3;
    const int ln   = lane >> 2;

    const int NT = Sn / 64;    // 32 key tiles

    auto issue_kv = [&](int kt, int s) {
        const float* kp = kb + (size_t)kt * 64 * HDn;
        const float* vp = vb + (size_t)kt * 64 * HDn;
        #pragma unroll
        for (int i = 0; i < 4; i++) {
            int lin = tid + i * 256;
            int r = lin >> 4, c4 = (lin & 15) << 2;
            cp16(&Ks[s * 64 * KS_ST + r * KS_ST + c4], kp + (size_t)r * HDn + c4);
            cp16(&Vs[s * 64 * VS_ST + r * VS_ST + c4], vp + (size_t)r * HDn + c4);
        }
        if (tid < 64) maskS[s][tid] = mask[b * Sn + kt * 64 + tid];
        cp_commit();
    };

    // ---- prologue: Q (group 0), KV stage 0 (group 1), KV stage 1 (group 2) ----
    #pragma unroll
    for (int i = 0; i < 8; i++) {
        int lin = tid + i * 256;
        int r = lin >> 4, c4 = (lin & 15) << 2;
        cp16(&Ps[r * QP_ST + c4], qb + (size_t)r * HDn + c4);
    }
    cp_commit();
    issue_kv(0, 0);
    issue_kv(1, 1);

    cp_wait<2>();          // Q arrived
    __syncthreads();

    // Q fragments -> tf32 registers, held for whole kernel
    uint32_t qf[8][4];
    #pragma unroll
    for (int ks = 0; ks < 8; ks++) {
        ldm_x4(qf[ks], &Ps[(warp * 16 + arow) * QP_ST + ks * 8 + acol]);
        #pragma unroll
        for (int j = 0; j < 4; j++) qf[ks][j] = u2tf32(qf[ks][j]);
    }
    __syncthreads();       // everyone done reading Q; Ps becomes P storage

    float o[8][4] = {};
    float m_i[2] = {-1e30f, -1e30f};
    float l_i[2] = {0.0f, 0.0f};

    for (int kt = 0; kt < NT; kt++) {
        const int s = kt & 1;
        if (kt + 1 < NT) cp_wait<1>(); else cp_wait<0>();
        __syncthreads();

        const float* KsS = Ks + s * 64 * KS_ST;
        const float* VsS = Vs + s * 64 * VS_ST;

        // ---- S = Q @ K^T ----
        float sacc[8][4] = {};
        #pragma unroll
        for (int ks = 0; ks < 8; ks++) {
            #pragma unroll
            for (int ni = 0; ni < 8; ni++) {
                uint32_t b0 = f2tf32(KsS[(ni * 8 + ln) * KS_ST + ks * 8 + lk]);
                uint32_t b1 = f2tf32(KsS[(ni * 8 + ln) * KS_ST + ks * 8 + 4 + lk]);
                mma_tf32(sacc[ni], qf[ks][0], qf[ks][1], qf[ks][2], qf[ks][3], b0, b1);
            }
        }

        // ---- online softmax on C-fragments; write P (tf32) into Ps ----
        #pragma unroll
        for (int rr = 0; rr < 2; rr++) {
            float sv[8][2];
            float mx = -1e30f;
            #pragma unroll
            for (int ni = 0; ni < 8; ni++) {
                int c = ni * 8 + lk * 2;
                float s0 = maskS[s][c]     ? sacc[ni][rr * 2 + 0] * scale + bias : -1e30f;
                float s1 = maskS[s][c + 1] ? sacc[ni][rr * 2 + 1] * scale + bias : -1e30f;
                sv[ni][0] = s0; sv[ni][1] = s1;
                mx = fmaxf(mx, fmaxf(s0, s1));
            }
            mx = fmaxf(mx, __shfl_xor_sync(0xffffffffu, mx, 1));
            mx = fmaxf(mx, __shfl_xor_sync(0xffffffffu, mx, 2));
            float m_new = fmaxf(m_i[rr], mx);

            float rs = 0.0f;
            int prow = (warp * 16 + ln + rr * 8) * QP_ST;
            #pragma unroll
            for (int ni = 0; ni < 8; ni++) {
                float p0 = __expf(sv[ni][0] - m_new);
                float p1 = __expf(sv[ni][1] - m_new);
                rs += p0 + p1;
                float2 pp;
                pp.x = __uint_as_float(f2tf32(p0));
                pp.y = __uint_as_float(f2tf32(p1));
                *(float2*)&Ps[prow + ni * 8 + lk * 2] = pp;
            }
            rs += __shfl_xor_sync(0xffffffffu, rs, 1);
            rs += __shfl_xor_sync(0xffffffffu, rs, 2);

            float alpha = __expf(m_i[rr] - m_new);
            l_i[rr] = l_i[rr] * alpha + rs;
            m_i[rr] = m_new;
            #pragma unroll
            for (int ni = 0; ni < 8; ni++) {
                o[ni][rr * 2 + 0] *= alpha;
                o[ni][rr * 2 + 1] *= alpha;
            }
        }
        __syncwarp();   // per-warp P rows: STS -> ldmatrix ordering

        // ---- O += P @ V ----
        #pragma unroll
        for (int ks = 0; ks < 8; ks++) {
            uint32_t pf[4];
            ldm_x4(pf, &Ps[(warp * 16 + arow) * QP_ST + ks * 8 + acol]);
            #pragma unroll
            for (int ni = 0; ni < 8; ni++) {
                uint32_t b0 = f2tf32(VsS[(ks * 8 + lk)     * VS_ST + ni * 8 + ln]);
                uint32_t b1 = f2tf32(VsS[(ks * 8 + 4 + lk) * VS_ST + ni * 8 + ln]);
                mma_tf32(o[ni], pf[0], pf[1], pf[2], pf[3], b0, b1);
            }
        }

        __syncthreads();               // all warps done with stage s buffers
        if (kt + 2 < NT) issue_kv(kt + 2, s);
    }

    // ---- finalize, write [B,S,D] ----
    #pragma unroll
    for (int rr = 0; rr < 2; rr++) {
        float inv = 1.0f / l_i[rr];
        int q = q0 + warp * 16 + ln + rr * 8;
        #pragma unroll
        for (int ni = 0; ni < 8; ni++) {
            float2 ov;
            ov.x = o[ni][rr * 2 + 0] * inv;
            ov.y = o[ni][rr * 2 + 1] * inv;
            *(float2*)&g_attn[((size_t)(b * Sn + q)) * Dn + h * HDn + ni * 8 + lk * 2] = ov;
        }
    }
}

// ---------------------------------------------------------------------------
// Launch
// ---------------------------------------------------------------------------
extern "C" void kernel_launch(void* const* d_in, const int* in_sizes, int n_in,
                              void* d_out, int out_size) {
    const float* x    = (const float*)d_in[0];
    const float* te   = (const float*)d_in[1];
    const int*   mask = (const int*)  d_in[2];
    const float* Wq   = (const float*)d_in[3];
    const float* bq   = (const float*)d_in[4];
    const float* Wk   = (const float*)d_in[5];
    const float* bk   = (const float*)d_in[6];
    const float* Wv   = (const float*)d_in[7];
    const float* bv   = (const float*)d_in[8];
    const float* Wo   = (const float*)d_in[9];
    const float* bo   = (const float*)d_in[10];
    const float* Wt   = (const float*)d_in[11];
    const float* bt   = (const float*)d_in[12];
    float* out = (float*)d_out;

    (void)in_sizes; (void)n_in; (void)out_size;

    cudaFuncSetAttribute(attn_tc_kernel,
                         cudaFuncAttributeMaxDynamicSharedMemorySize,
                         ATTN_SMEM_BYTES);

    task_bias_kernel<<<1, 64>>>(te, Wt, bt);
    qkv_gemm_tc_kernel<<<dim3(Dn / 128, Mn / 128, 3), 256>>>(x, Wq, bq, Wk, bk, Wv, bv);
    attn_tc_kernel<<<dim3(Sn / 128, Hn, Bn), 256, ATTN_SMEM_BYTES>>>(mask);
    out_gemm_tc_kernel<<<dim3(Dn / 128, Mn / 128, 1), 256>>>(Wo, bo, out);
}

// round 13
// speedup vs baseline: 1.0007x; 1.0007x over previous
#include <cuda_runtime.h>
#include <math.h>
#include <stdint.h>

// Problem constants
#define Bn  4
#define Sn  2048
#define Dn  1024
#define Hn  16
#define HDn 64
#define TEn 64
#define Mn  (Bn * Sn)   // 8192

// ---------------------------------------------------------------------------
// Scratch
// ---------------------------------------------------------------------------
__device__ float g_q[Bn * Hn * Sn * HDn];      // [B,H,S,HD]
__device__ float g_k[Bn * Hn * Sn * HDn];
__device__ float g_v[Bn * Hn * Sn * HDn];
__device__ float g_attn[Bn * Sn * Dn];         // [B,S,D]
__device__ float g_bias[Bn * Hn];

// ---------------------------------------------------------------------------
// PTX helpers
// ---------------------------------------------------------------------------
__device__ __forceinline__ uint32_t f2tf32(float f) {
    uint32_t u;
    asm("cvt.rna.tf32.f32 %0, %1;" : "=r"(u) : "f"(f));
    return u;
}
__device__ __forceinline__ uint32_t u2tf32(uint32_t x) {
    uint32_t y;
    asm("cvt.rna.tf32.f32 %0, %1;" : "=r"(y) : "f"(__uint_as_float(x)));
    return y;
}

__device__ __forceinline__ void mma_tf32(float c[4],
                                         uint32_t a0, uint32_t a1, uint32_t a2, uint32_t a3,
                                         uint32_t b0, uint32_t b1) {
    asm volatile(
        "mma.sync.aligned.m16n8k8.row.col.f32.tf32.tf32.f32 "
        "{%0,%1,%2,%3}, {%4,%5,%6,%7}, {%8,%9}, {%0,%1,%2,%3};"
        : "+f"(c[0]), "+f"(c[1]), "+f"(c[2]), "+f"(c[3])
        : "r"(a0), "r"(a1), "r"(a2), "r"(a3), "r"(b0), "r"(b1));
}

__device__ __forceinline__ void ldm_x4(uint32_t r[4], const float* p) {
    uint32_t addr = (uint32_t)__cvta_generic_to_shared(p);
    asm volatile("ldmatrix.sync.aligned.m8n8.x4.shared.b16 {%0,%1,%2,%3}, [%4];"
                 : "=r"(r[0]), "=r"(r[1]), "=r"(r[2]), "=r"(r[3])
                 : "r"(addr));
}

__device__ __forceinline__ void cp16(float* dst, const float* src) {
    uint32_t d = (uint32_t)__cvta_generic_to_shared(dst);
    asm volatile("cp.async.cg.shared.global [%0], [%1], 16;" :: "r"(d), "l"(src));
}
__device__ __forceinline__ void cp_commit() {
    asm volatile("cp.async.commit_group;" ::: "memory");
}
template<int N>
__device__ __forceinline__ void cp_wait() {
    asm volatile("cp.async.wait_group %0;" :: "n"(N) : "memory");
}

// ---------------------------------------------------------------------------
// Kernel 1: task bias  (B,TE) @ (TE,H) + bt -> (B,H)
// ---------------------------------------------------------------------------
__global__ void task_bias_kernel(const float* __restrict__ te,
                                 const float* __restrict__ Wt,
                                 const float* __restrict__ bt) {
    int t = threadIdx.x;
    if (t < Bn * Hn) {
        int b = t / Hn, h = t % Hn;
        float acc = bt[h];
        #pragma unroll 8
        for (int i = 0; i < TEn; i++) acc += te[b * TEn + i] * Wt[i * Hn + h];
        g_bias[t] = acc;
    }
}

// ---------------------------------------------------------------------------
// tf32 tensor-core GEMM, cp.async double-buffered.
// BM=128, BN=128, BK=32, 256 threads = 8 warps (4M x 2N), warp tile 32x64.
// Raw fp32 in smem; tf32 conversion happens on register fragments.
// ---------------------------------------------------------------------------
#define AS_ST 36     // A smem stride (floats); 144B rows, 16B aligned
#define BS_ST 136    // B smem stride; 136 % 32 == 8 -> conflict-free B-frag LDS

template<int SCATTER>
__device__ __forceinline__ void gemm_tf32_body(
    const float* __restrict__ A, const float* __restrict__ W,
    const float* __restrict__ bias, float* __restrict__ out)
{
    __shared__ float As[2][128 * AS_ST];
    __shared__ float Bs[2][32 * BS_ST];

    const int tid  = threadIdx.x;
    const int lane = tid & 31;
    const int warp = tid >> 5;
    const int wm   = warp & 3;
    const int wn   = warp >> 2;
    const int m0   = blockIdx.y * 128;
    const int n0   = blockIdx.x * 128;

    const int arow = (lane < 16) ? lane : lane - 16;
    const int acol = (lane < 16) ? 0 : 4;
    const int lk   = lane & 3;
    const int ln   = lane >> 2;

    float acc[2][8][4] = {};

    const int NK = Dn / 32;   // 32 k-steps

    auto issue = [&](int kk, int s) {
        #pragma unroll
        for (int i = 0; i < 4; i++) {
            int lin = tid + i * 256;
            int r = lin >> 3, c4 = (lin & 7) << 2;
            cp16(&As[s][r * AS_ST + c4], &A[(size_t)(m0 + r) * Dn + kk + c4]);
        }
        #pragma unroll
        for (int i = 0; i < 4; i++) {
            int lin = tid + i * 256;
            int r = lin >> 5, c4 = (lin & 31) << 2;
            cp16(&Bs[s][r * BS_ST + c4], &W[(size_t)(kk + r) * Dn + n0 + c4]);
        }
        cp_commit();
    };

    issue(0, 0);
    issue(32, 1);

    for (int kstep = 0; kstep < NK; kstep++) {
        const int s = kstep & 1;
        if (kstep + 1 < NK) cp_wait<1>(); else cp_wait<0>();
        __syncthreads();

        #pragma unroll
        for (int ks = 0; ks < 4; ks++) {
            const int k0 = ks * 8;
            uint32_t af[2][4];
            #pragma unroll
            for (int mi = 0; mi < 2; mi++) {
                ldm_x4(af[mi], &As[s][(wm * 32 + mi * 16 + arow) * AS_ST + k0 + acol]);
                #pragma unroll
                for (int j = 0; j < 4; j++) af[mi][j] = u2tf32(af[mi][j]);
            }
            uint32_t bf0[8], bf1[8];
            #pragma unroll
            for (int ni = 0; ni < 8; ni++) {
                int n = wn * 64 + ni * 8 + ln;
                bf0[ni] = f2tf32(Bs[s][(k0 + lk)     * BS_ST + n]);
                bf1[ni] = f2tf32(Bs[s][(k0 + 4 + lk) * BS_ST + n]);
            }
            #pragma unroll
            for (int mi = 0; mi < 2; mi++)
                #pragma unroll
                for (int ni = 0; ni < 8; ni++)
                    mma_tf32(acc[mi][ni], af[mi][0], af[mi][1], af[mi][2], af[mi][3],
                             bf0[ni], bf1[ni]);
        }
        __syncthreads();
        if (kstep + 2 < NK) issue((kstep + 2) * 32, s);
    }

    // epilogue
    #pragma unroll
    for (int mi = 0; mi < 2; mi++) {
        #pragma unroll
        for (int ni = 0; ni < 8; ni++) {
            int n = n0 + wn * 64 + ni * 8 + lk * 2;
            float bb0 = bias[n], bb1 = bias[n + 1];
            #pragma unroll
            for (int rr = 0; rr < 2; rr++) {
                int m = m0 + wm * 32 + mi * 16 + ln + rr * 8;
                float2 o;
                o.x = acc[mi][ni][rr * 2 + 0] + bb0;
                o.y = acc[mi][ni][rr * 2 + 1] + bb1;
                if (SCATTER) {
                    int b = m >> 11, sI = m & (Sn - 1);
                    int h = n >> 6, hd = n & 63;
                    *(float2*)&out[((size_t)(b * Hn + h) * Sn + sI) * HDn + hd] = o;
                } else {
                    *(float2*)&out[(size_t)m * Dn + n] = o;
                }
            }
        }
    }
}

__global__ __launch_bounds__(256, 2)
void qkv_gemm_tc_kernel(const float* __restrict__ x,
                        const float* __restrict__ Wq, const float* __restrict__ bq,
                        const float* __restrict__ Wk, const float* __restrict__ bk,
                        const float* __restrict__ Wv, const float* __restrict__ bv) {
    const float* W; const float* bias; float* out;
    if (blockIdx.z == 0)      { W = Wq; bias = bq; out = g_q; }
    else if (blockIdx.z == 1) { W = Wk; bias = bk; out = g_k; }
    else                      { W = Wv; bias = bv; out = g_v; }
    gemm_tf32_body<1>(x, W, bias, out);
}

__global__ __launch_bounds__(256, 2)
void out_gemm_tc_kernel(const float* __restrict__ Wo,
                        const float* __restrict__ bo,
                        float* __restrict__ out) {
    gemm_tf32_body<0>(g_attn, Wo, bo, out);
}

// ---------------------------------------------------------------------------
// Kernel 3: tensor-core flash attention, 128 q-rows / 8 warps per block,
// cp.async double-buffered K/V tiles (64 keys each).
// Smem: Ps 128x68 (holds raw Q during prologue, then tf32 P),
//       Ks[2] 64x68 raw fp32, Vs[2] 64x72 raw fp32.
// tf32 conversion on register fragments.
// ---------------------------------------------------------------------------
#define QP_ST 68
#define KS_ST 68
#define VS_ST 72
#define ATTN_SMEM_FLOATS (128 * QP_ST + 2 * 64 * KS_ST + 2 * 64 * VS_ST)
#define ATTN_SMEM_BYTES  (ATTN_SMEM_FLOATS * 4)

__global__ __launch_bounds__(256, 1)
void attn_tc_kernel(const int* __restrict__ mask) {
    extern __shared__ float sm[];
    float* Ps = sm;                                 // 128*68
    float* Ks = sm + 128 * QP_ST;                   // 2 * 64*68
    float* Vs = Ks + 2 * 64 * KS_ST;                // 2 * 64*72
    __shared__ int maskS[2][64];

    const int tid  = threadIdx.x;
    const int lane = tid & 31;
    const int warp = tid >> 5;                      // 0..7
    const int q0   = blockIdx.x * 128;
    const int h    = blockIdx.y;
    const int b    = blockIdx.z;

    const float* qb = g_q + ((size_t)(b * Hn + h) * Sn + q0) * HDn;
    const float* kb = g_k + ((size_t)(b * Hn + h) * Sn) * HDn;
    const float* vb = g_v + ((size_t)(b * Hn + h) * Sn) * HDn;
    const float bias  = g_bias[b * Hn + h];
    const float scale = 0.125f;

    const int arow = (lane < 16) ? lane : lane - 16;
    const int acol = (lane < 16) ? 0 : 4;
    const int lk   = lane & 3;
    const int ln   = lane >> 2;

    const int NT = Sn / 64;    // 32 key tiles

    auto issue_kv = [&](int kt, int s) {
        const float* kp = kb + (size_t)kt * 64 * HDn;
        const float* vp = vb + (size_t)kt * 64 * HDn;
        #pragma unroll
        for (int i = 0; i < 4; i++) {
            int lin = tid + i * 256;
            int r = lin >> 4, c4 = (lin & 15) << 2;
            cp16(&Ks[s * 64 * KS_ST + r * KS_ST + c4], kp + (size_t)r * HDn + c4);
            cp16(&Vs[s * 64 * VS_ST + r * VS_ST + c4], vp + (size_t)r * HDn + c4);
        }
        if (tid < 64) maskS[s][tid] = mask[b * Sn + kt * 64 + tid];
        cp_commit();
    };

    // ---- prologue: Q (group 0), KV stage 0 (group 1), KV stage 1 (group 2) ----
    #pragma unroll
    for (int i = 0; i < 8; i++) {
        int lin = tid + i * 256;
        int r = lin >> 4, c4 = (lin & 15) << 2;
        cp16(&Ps[r * QP_ST + c4], qb + (size_t)r * HDn + c4);
    }
    cp_commit();
    issue_kv(0, 0);
    issue_kv(1, 1);

    cp_wait<2>();          // Q arrived
    __syncthreads();

    // Q fragments -> tf32 registers, held for whole kernel
    uint32_t qf[8][4];
    #pragma unroll
    for (int ks = 0; ks < 8; ks++) {
        ldm_x4(qf[ks], &Ps[(warp * 16 + arow) * QP_ST + ks * 8 + acol]);
        #pragma unroll
        for (int j = 0; j < 4; j++) qf[ks][j] = u2tf32(qf[ks][j]);
    }
    __syncthreads();       // everyone done reading Q; Ps becomes P storage

    float o[8][4] = {};
    float m_i[2] = {-1e30f, -1e30f};
    float l_i[2] = {0.0f, 0.0f};

    for (int kt = 0; kt < NT; kt++) {
        const int s = kt & 1;
        if (kt + 1 < NT) cp_wait<1>(); else cp_wait<0>();
        __syncthreads();

        const float* KsS = Ks + s * 64 * KS_ST;
        const float* VsS = Vs + s * 64 * VS_ST;

        // ---- S = Q @ K^T ----
        float sacc[8][4] = {};
        #pragma unroll
        for (int ks = 0; ks < 8; ks++) {
            #pragma unroll
            for (int ni = 0; ni < 8; ni++) {
                uint32_t b0 = f2tf32(KsS[(ni * 8 + ln) * KS_ST + ks * 8 + lk]);
                uint32_t b1 = f2tf32(KsS[(ni * 8 + ln) * KS_ST + ks * 8 + 4 + lk]);
                mma_tf32(sacc[ni], qf[ks][0], qf[ks][1], qf[ks][2], qf[ks][3], b0, b1);
            }
        }

        // ---- online softmax on C-fragments; write P (tf32) into Ps ----
        #pragma unroll
        for (int rr = 0; rr < 2; rr++) {
            float sv[8][2];
            float mx = -1e30f;
            #pragma unroll
            for (int ni = 0; ni < 8; ni++) {
                int c = ni * 8 + lk * 2;
                float s0 = maskS[s][c]     ? sacc[ni][rr * 2 + 0] * scale + bias : -1e30f;
                float s1 = maskS[s][c + 1] ? sacc[ni][rr * 2 + 1] * scale + bias : -1e30f;
                sv[ni][0] = s0; sv[ni][1] = s1;
                mx = fmaxf(mx, fmaxf(s0, s1));
            }
            mx = fmaxf(mx, __shfl_xor_sync(0xffffffffu, mx, 1));
            mx = fmaxf(mx, __shfl_xor_sync(0xffffffffu, mx, 2));
            float m_new = fmaxf(m_i[rr], mx);

            float rs = 0.0f;
            int prow = (warp * 16 + ln + rr * 8) * QP_ST;
            #pragma unroll
            for (int ni = 0; ni < 8; ni++) {
                float p0 = __expf(sv[ni][0] - m_new);
                float p1 = __expf(sv[ni][1] - m_new);
                rs += p0 + p1;
                float2 pp;
                pp.x = __uint_as_float(f2tf32(p0));
                pp.y = __uint_as_float(f2tf32(p1));
                *(float2*)&Ps[prow + ni * 8 + lk * 2] = pp;
            }
            rs += __shfl_xor_sync(0xffffffffu, rs, 1);
            rs += __shfl_xor_sync(0xffffffffu, rs, 2);

            float alpha = __expf(m_i[rr] - m_new);
            l_i[rr] = l_i[rr] * alpha + rs;
            m_i[rr] = m_new;
            #pragma unroll
            for (int ni = 0; ni < 8; ni++) {
                o[ni][rr * 2 + 0] *= alpha;
                o[ni][rr * 2 + 1] *= alpha;
            }
        }
        __syncwarp();   // per-warp P rows: STS -> ldmatrix ordering

        // ---- O += P @ V ----
        #pragma unroll
        for (int ks = 0; ks < 8; ks++) {
            uint32_t pf[4];
            ldm_x4(pf, &Ps[(warp * 16 + arow) * QP_ST + ks * 8 + acol]);
            #pragma unroll
            for (int ni = 0; ni < 8; ni++) {
                uint32_t b0 = f2tf32(VsS[(ks * 8 + lk)     * VS_ST + ni * 8 + ln]);
                uint32_t b1 = f2tf32(VsS[(ks * 8 + 4 + lk) * VS_ST + ni * 8 + ln]);
                mma_tf32(o[ni], pf[0], pf[1], pf[2], pf[3], b0, b1);
            }
        }

        __syncthreads();               // all warps done with stage s buffers
        if (kt + 2 < NT) issue_kv(kt + 2, s);
    }

    // ---- finalize, write [B,S,D] ----
    #pragma unroll
    for (int rr = 0; rr < 2; rr++) {
        float inv = 1.0f / l_i[rr];
        int q = q0 + warp * 16 + ln + rr * 8;
        #pragma unroll
        for (int ni = 0; ni < 8; ni++) {
            float2 ov;
            ov.x = o[ni][rr * 2 + 0] * inv;
            ov.y = o[ni][rr * 2 + 1] * inv;
            *(float2*)&g_attn[((size_t)(b * Sn + q)) * Dn + h * HDn + ni * 8 + lk * 2] = ov;
        }
    }
}

// ---------------------------------------------------------------------------
// Launch
// ---------------------------------------------------------------------------
extern "C" void kernel_launch(void* const* d_in, const int* in_sizes, int n_in,
                              void* d_out, int out_size) {
    const float* x    = (const float*)d_in[0];
    const float* te   = (const float*)d_in[1];
    const int*   mask = (const int*)  d_in[2];
    const float* Wq   = (const float*)d_in[3];
    const float* bq   = (const float*)d_in[4];
    const float* Wk   = (const float*)d_in[5];
    const float* bk   = (const float*)d_in[6];
    const float* Wv   = (const float*)d_in[7];
    const float* bv   = (const float*)d_in[8];
    const float* Wo   = (const float*)d_in[9];
    const float* bo   = (const float*)d_in[10];
    const float* Wt   = (const float*)d_in[11];
    const float* bt   = (const float*)d_in[12];
    float* out = (float*)d_out;

    (void)in_sizes; (void)n_in; (void)out_size;

    cudaFuncSetAttribute(attn_tc_kernel,
                         cudaFuncAttributeMaxDynamicSharedMemorySize,
                         ATTN_SMEM_BYTES);

    task_bias_kernel<<<1, 64>>>(te, Wt, bt);
    qkv_gemm_tc_kernel<<<dim3(Dn / 128, Mn / 128, 3), 256>>>(x, Wq, bq, Wk, bk, Wv, bv);
    attn_tc_kernel<<<dim3(Sn / 128, Hn, Bn), 256, ATTN_SMEM_BYTES>>>(mask);
    out_gemm_tc_kernel<<<dim3(Dn / 128, Mn / 128, 1), 256>>>(Wo, bo, out);
}

// round 14
// speedup vs baseline: 1.2000x; 1.1992x over previous
#include <cuda_runtime.h>
#include <math.h>
#include <stdint.h>

// Problem constants
#define Bn  4
#define Sn  2048
#define Dn  1024
#define Hn  16
#define HDn 64
#define TEn 64
#define Mn  (Bn * Sn)   // 8192

// ---------------------------------------------------------------------------
// Scratch
// ---------------------------------------------------------------------------
__device__ float g_x[Mn * Dn];                 // tf32-rounded x
__device__ float g_w[4][Dn * Dn];              // tf32-rounded Wq,Wk,Wv,Wo
__device__ float g_q[Bn * Hn * Sn * HDn];      // [B,H,S,HD], tf32-rounded
__device__ float g_k[Bn * Hn * Sn * HDn];
__device__ float g_v[Bn * Hn * Sn * HDn];
__device__ float g_attn[Bn * Sn * Dn];         // [B,S,D], tf32-rounded
__device__ float g_bias[Bn * Hn];

// ---------------------------------------------------------------------------
// PTX helpers
// ---------------------------------------------------------------------------
__device__ __forceinline__ uint32_t f2tf32(float f) {
    uint32_t u;
    asm("cvt.rna.tf32.f32 %0, %1;" : "=r"(u) : "f"(f));
    return u;
}

__device__ __forceinline__ void mma_tf32(float c[4],
                                         uint32_t a0, uint32_t a1, uint32_t a2, uint32_t a3,
                                         uint32_t b0, uint32_t b1) {
    asm volatile(
        "mma.sync.aligned.m16n8k8.row.col.f32.tf32.tf32.f32 "
        "{%0,%1,%2,%3}, {%4,%5,%6,%7}, {%8,%9}, {%0,%1,%2,%3};"
        : "+f"(c[0]), "+f"(c[1]), "+f"(c[2]), "+f"(c[3])
        : "r"(a0), "r"(a1), "r"(a2), "r"(a3), "r"(b0), "r"(b1));
}

__device__ __forceinline__ void ldm_x4(uint32_t r[4], const float* p) {
    uint32_t addr = (uint32_t)__cvta_generic_to_shared(p);
    asm volatile("ldmatrix.sync.aligned.m8n8.x4.shared.b16 {%0,%1,%2,%3}, [%4];"
                 : "=r"(r[0]), "=r"(r[1]), "=r"(r[2]), "=r"(r[3])
                 : "r"(addr));
}

__device__ __forceinline__ void cp16(float* dst, const float* src) {
    uint32_t d = (uint32_t)__cvta_generic_to_shared(dst);
    asm volatile("cp.async.cg.shared.global [%0], [%1], 16;" :: "r"(d), "l"(src));
}
__device__ __forceinline__ void cp_commit() {
    asm volatile("cp.async.commit_group;" ::: "memory");
}
template<int N>
__device__ __forceinline__ void cp_wait() {
    asm volatile("cp.async.wait_group %0;" :: "n"(N) : "memory");
}

// ---------------------------------------------------------------------------
// Kernel 0: pre-round x and weights to tf32 (low 13 mantissa bits zeroed).
// After this, mma can consume raw bits with no in-loop cvt, bit-identical
// to cvt-ing at fragment load.
// ---------------------------------------------------------------------------
__global__ void preround_kernel(const float* __restrict__ x,
                                const float* __restrict__ Wq,
                                const float* __restrict__ Wk,
                                const float* __restrict__ Wv,
                                const float* __restrict__ Wo) {
    const float* src; float* dst; size_t n4;
    switch (blockIdx.y) {
        case 0: src = x;  dst = g_x;    n4 = (size_t)Mn * Dn / 4; break;
        case 1: src = Wq; dst = g_w[0]; n4 = (size_t)Dn * Dn / 4; break;
        case 2: src = Wk; dst = g_w[1]; n4 = (size_t)Dn * Dn / 4; break;
        case 3: src = Wv; dst = g_w[2]; n4 = (size_t)Dn * Dn / 4; break;
        default: src = Wo; dst = g_w[3]; n4 = (size_t)Dn * Dn / 4; break;
    }
    for (size_t i = (size_t)blockIdx.x * blockDim.x + threadIdx.x;
         i < n4; i += (size_t)gridDim.x * blockDim.x) {
        float4 v = ((const float4*)src)[i];
        uint4 o;
        o.x = f2tf32(v.x); o.y = f2tf32(v.y);
        o.z = f2tf32(v.z); o.w = f2tf32(v.w);
        ((uint4*)dst)[i] = o;
    }
}

// ---------------------------------------------------------------------------
// Kernel 1: task bias  (B,TE) @ (TE,H) + bt -> (B,H)
// ---------------------------------------------------------------------------
__global__ void task_bias_kernel(const float* __restrict__ te,
                                 const float* __restrict__ Wt,
                                 const float* __restrict__ bt) {
    int t = threadIdx.x;
    if (t < Bn * Hn) {
        int b = t / Hn, h = t % Hn;
        float acc = bt[h];
        #pragma unroll 8
        for (int i = 0; i < TEn; i++) acc += te[b * TEn + i] * Wt[i * Hn + h];
        g_bias[t] = acc;
    }
}

// ---------------------------------------------------------------------------
// tf32 tensor-core GEMM, cp.async double-buffered, NO in-loop cvt
// (operands pre-rounded). BM=128, BN=128, BK=32, 8 warps, warp tile 32x64.
// ROUND_OUT: tf32-round the stored result (for q/k/v which feed more mmas).
// ---------------------------------------------------------------------------
#define AS_ST 36     // A smem stride (floats)
#define BS_ST 136    // B smem stride; 136 % 32 == 8 -> conflict-free B-frag LDS

template<int SCATTER, int ROUND_OUT>
__device__ __forceinline__ void gemm_tf32_body(
    const float* __restrict__ A, const float* __restrict__ W,
    const float* __restrict__ bias, float* __restrict__ out)
{
    __shared__ float As[2][128 * AS_ST];
    __shared__ float Bs[2][32 * BS_ST];

    const int tid  = threadIdx.x;
    const int lane = tid & 31;
    const int warp = tid >> 5;
    const int wm   = warp & 3;
    const int wn   = warp >> 2;
    const int m0   = blockIdx.y * 128;
    const int n0   = blockIdx.x * 128;

    const int arow = (lane < 16) ? lane : lane - 16;
    const int acol = (lane < 16) ? 0 : 4;
    const int lk   = lane & 3;
    const int ln   = lane >> 2;

    float acc[2][8][4] = {};

    const int NK = Dn / 32;

    auto issue = [&](int kk, int s) {
        #pragma unroll
        for (int i = 0; i < 4; i++) {
            int lin = tid + i * 256;
            int r = lin >> 3, c4 = (lin & 7) << 2;
            cp16(&As[s][r * AS_ST + c4], &A[(size_t)(m0 + r) * Dn + kk + c4]);
        }
        #pragma unroll
        for (int i = 0; i < 4; i++) {
            int lin = tid + i * 256;
            int r = lin >> 5, c4 = (lin & 31) << 2;
            cp16(&Bs[s][r * BS_ST + c4], &W[(size_t)(kk + r) * Dn + n0 + c4]);
        }
        cp_commit();
    };

    issue(0, 0);
    issue(32, 1);

    for (int kstep = 0; kstep < NK; kstep++) {
        const int s = kstep & 1;
        if (kstep + 1 < NK) cp_wait<1>(); else cp_wait<0>();
        __syncthreads();

        #pragma unroll
        for (int ks = 0; ks < 4; ks++) {
            const int k0 = ks * 8;
            uint32_t af[2][4];
            #pragma unroll
            for (int mi = 0; mi < 2; mi++)
                ldm_x4(af[mi], &As[s][(wm * 32 + mi * 16 + arow) * AS_ST + k0 + acol]);
            uint32_t bf0[8], bf1[8];
            #pragma unroll
            for (int ni = 0; ni < 8; ni++) {
                int n = wn * 64 + ni * 8 + ln;
                bf0[ni] = __float_as_uint(Bs[s][(k0 + lk)     * BS_ST + n]);
                bf1[ni] = __float_as_uint(Bs[s][(k0 + 4 + lk) * BS_ST + n]);
            }
            #pragma unroll
            for (int mi = 0; mi < 2; mi++)
                #pragma unroll
                for (int ni = 0; ni < 8; ni++)
                    mma_tf32(acc[mi][ni], af[mi][0], af[mi][1], af[mi][2], af[mi][3],
                             bf0[ni], bf1[ni]);
        }
        __syncthreads();
        if (kstep + 2 < NK) issue((kstep + 2) * 32, s);
    }

    // epilogue
    #pragma unroll
    for (int mi = 0; mi < 2; mi++) {
        #pragma unroll
        for (int ni = 0; ni < 8; ni++) {
            int n = n0 + wn * 64 + ni * 8 + lk * 2;
            float bb0 = bias[n], bb1 = bias[n + 1];
            #pragma unroll
            for (int rr = 0; rr < 2; rr++) {
                int m = m0 + wm * 32 + mi * 16 + ln + rr * 8;
                float2 o;
                o.x = acc[mi][ni][rr * 2 + 0] + bb0;
                o.y = acc[mi][ni][rr * 2 + 1] + bb1;
                if (ROUND_OUT) {
                    o.x = __uint_as_float(f2tf32(o.x));
                    o.y = __uint_as_float(f2tf32(o.y));
                }
                if (SCATTER) {
                    int b = m >> 11, sI = m & (Sn - 1);
                    int h = n >> 6, hd = n & 63;
                    *(float2*)&out[((size_t)(b * Hn + h) * Sn + sI) * HDn + hd] = o;
                } else {
                    *(float2*)&out[(size_t)m * Dn + n] = o;
                }
            }
        }
    }
}

__global__ __launch_bounds__(256, 2)
void qkv_gemm_tc_kernel(const float* __restrict__ bq,
                        const float* __restrict__ bk,
                        const float* __restrict__ bv) {
    const float* bias; float* out;
    if (blockIdx.z == 0)      { bias = bq; out = g_q; }
    else if (blockIdx.z == 1) { bias = bk; out = g_k; }
    else                      { bias = bv; out = g_v; }
    gemm_tf32_body<1, 1>(g_x, g_w[blockIdx.z], bias, out);
}

__global__ __launch_bounds__(256, 2)
void out_gemm_tc_kernel(const float* __restrict__ bo,
                        float* __restrict__ out) {
    gemm_tf32_body<0, 0>(g_attn, g_w[3], bo, out);
}

// ---------------------------------------------------------------------------
// Kernel 3: tensor-core flash attention, 128 q-rows / 8 warps per block,
// cp.async double-buffered K/V. Q/K/V pre-rounded tf32 -> no in-loop cvt
// except on P. Occupancy 2 (regs capped at 128).
// ---------------------------------------------------------------------------
#define QP_ST 68
#define KS_ST 68
#define VS_ST 72
#define ATTN_SMEM_FLOATS (128 * QP_ST + 2 * 64 * KS_ST + 2 * 64 * VS_ST)
#define ATTN_SMEM_BYTES  (ATTN_SMEM_FLOATS * 4)

__global__ __launch_bounds__(256, 2)
void attn_tc_kernel(const int* __restrict__ mask) {
    extern __shared__ float sm[];
    float* Ps = sm;                                 // 128*68
    float* Ks = sm + 128 * QP_ST;                   // 2 * 64*68
    float* Vs = Ks + 2 * 64 * KS_ST;                // 2 * 64*72
    __shared__ int maskS[2][64];

    const int tid  = threadIdx.x;
    const int lane = tid & 31;
    const int warp = tid >> 5;
    const int q0   = blockIdx.x * 128;
    const int h    = blockIdx.y;
    const int b    = blockIdx.z;

    const float* qb = g_q + ((size_t)(b * Hn + h) * Sn + q0) * HDn;
    const float* kb = g_k + ((size_t)(b * Hn + h) * Sn) * HDn;
    const float* vb = g_v + ((size_t)(b * Hn + h) * Sn) * HDn;
    const float bias  = g_bias[b * Hn + h];
    const float scale = 0.125f;

    const int arow = (lane < 16) ? lane : lane - 16;
    const int acol = (lane < 16) ? 0 : 4;
    const int lk   = lane & 3;
    const int ln   = lane >> 2;

    const int NT = Sn / 64;

    auto issue_kv = [&](int kt, int s) {
        const float* kp = kb + (size_t)kt * 64 * HDn;
        const float* vp = vb + (size_t)kt * 64 * HDn;
        #pragma unroll
        for (int i = 0; i < 4; i++) {
            int lin = tid + i * 256;
            int r = lin >> 4, c4 = (lin & 15) << 2;
            cp16(&Ks[s * 64 * KS_ST + r * KS_ST + c4], kp + (size_t)r * HDn + c4);
            cp16(&Vs[s * 64 * VS_ST + r * VS_ST + c4], vp + (size_t)r * HDn + c4);
        }
        if (tid < 64) maskS[s][tid] = mask[b * Sn + kt * 64 + tid];
        cp_commit();
    };

    // prologue: Q (group 0), KV stage 0 (group 1), KV stage 1 (group 2)
    #pragma unroll
    for (int i = 0; i < 8; i++) {
        int lin = tid + i * 256;
        int r = lin >> 4, c4 = (lin & 15) << 2;
        cp16(&Ps[r * QP_ST + c4], qb + (size_t)r * HDn + c4);
    }
    cp_commit();
    issue_kv(0, 0);
    issue_kv(1, 1);

    cp_wait<2>();
    __syncthreads();

    // Q fragments (already tf32-rounded) -> registers, held for whole kernel
    uint32_t qf[8][4];
    #pragma unroll
    for (int ks = 0; ks < 8; ks++)
        ldm_x4(qf[ks], &Ps[(warp * 16 + arow) * QP_ST + ks * 8 + acol]);
    __syncthreads();       // Ps becomes P storage

    float o[8][4] = {};
    float m_i[2] = {-1e30f, -1e30f};
    float l_i[2] = {0.0f, 0.0f};

    for (int kt = 0; kt < NT; kt++) {
        const int s = kt & 1;
        if (kt + 1 < NT) cp_wait<1>(); else cp_wait<0>();
        __syncthreads();

        const float* KsS = Ks + s * 64 * KS_ST;
        const float* VsS = Vs + s * 64 * VS_ST;

        // ---- S = Q @ K^T ----
        float sacc[8][4] = {};
        #pragma unroll
        for (int ks = 0; ks < 8; ks++) {
            #pragma unroll
            for (int ni = 0; ni < 8; ni++) {
                uint32_t b0 = __float_as_uint(KsS[(ni * 8 + ln) * KS_ST + ks * 8 + lk]);
                uint32_t b1 = __float_as_uint(KsS[(ni * 8 + ln) * KS_ST + ks * 8 + 4 + lk]);
                mma_tf32(sacc[ni], qf[ks][0], qf[ks][1], qf[ks][2], qf[ks][3], b0, b1);
            }
        }

        // ---- online softmax; P (tf32) into Ps ----
        #pragma unroll
        for (int rr = 0; rr < 2; rr++) {
            float sv[8][2];
            float mx = -1e30f;
            #pragma unroll
            for (int ni = 0; ni < 8; ni++) {
                int c = ni * 8 + lk * 2;
                float s0 = maskS[s][c]     ? sacc[ni][rr * 2 + 0] * scale + bias : -1e30f;
                float s1 = maskS[s][c + 1] ? sacc[ni][rr * 2 + 1] * scale + bias : -1e30f;
                sv[ni][0] = s0; sv[ni][1] = s1;
                mx = fmaxf(mx, fmaxf(s0, s1));
            }
            mx = fmaxf(mx, __shfl_xor_sync(0xffffffffu, mx, 1));
            mx = fmaxf(mx, __shfl_xor_sync(0xffffffffu, mx, 2));
            float m_new = fmaxf(m_i[rr], mx);

            float rs = 0.0f;
            int prow = (warp * 16 + ln + rr * 8) * QP_ST;
            #pragma unroll
            for (int ni = 0; ni < 8; ni++) {
                float p0 = __expf(sv[ni][0] - m_new);
                float p1 = __expf(sv[ni][1] - m_new);
                rs += p0 + p1;
                float2 pp;
                pp.x = __uint_as_float(f2tf32(p0));
                pp.y = __uint_as_float(f2tf32(p1));
                *(float2*)&Ps[prow + ni * 8 + lk * 2] = pp;
            }
            rs += __shfl_xor_sync(0xffffffffu, rs, 1);
            rs += __shfl_xor_sync(0xffffffffu, rs, 2);

            float alpha = __expf(m_i[rr] - m_new);
            l_i[rr] = l_i[rr] * alpha + rs;
            m_i[rr] = m_new;
            #pragma unroll
            for (int ni = 0; ni < 8; ni++) {
                o[ni][rr * 2 + 0] *= alpha;
                o[ni][rr * 2 + 1] *= alpha;
            }
        }
        __syncwarp();

        // ---- O += P @ V ----
        #pragma unroll
        for (int ks = 0; ks < 8; ks++) {
            uint32_t pf[4];
            ldm_x4(pf, &Ps[(warp * 16 + arow) * QP_ST + ks * 8 + acol]);
            #pragma unroll
            for (int ni = 0; ni < 8; ni++) {
                uint32_t b0 = __float_as_uint(VsS[(ks * 8 + lk)     * VS_ST + ni * 8 + ln]);
                uint32_t b1 = __float_as_uint(VsS[(ks * 8 + 4 + lk) * VS_ST + ni * 8 + ln]);
                mma_tf32(o[ni], pf[0], pf[1], pf[2], pf[3], b0, b1);
            }
        }

        __syncthreads();
        if (kt + 2 < NT) issue_kv(kt + 2, s);
    }

    // ---- finalize, write [B,S,D] tf32-rounded (feeds out_gemm mma) ----
    #pragma unroll
    for (int rr = 0; rr < 2; rr++) {
        float inv = 1.0f / l_i[rr];
        int q = q0 + warp * 16 + ln + rr * 8;
        #pragma unroll
        for (int ni = 0; ni < 8; ni++) {
            float2 ov;
            ov.x = __uint_as_float(f2tf32(o[ni][rr * 2 + 0] * inv));
            ov.y = __uint_as_float(f2tf32(o[ni][rr * 2 + 1] * inv));
            *(float2*)&g_attn[((size_t)(b * Sn + q)) * Dn + h * HDn + ni * 8 + lk * 2] = ov;
        }
    }
}

// ---------------------------------------------------------------------------
// Launch
// ---------------------------------------------------------------------------
extern "C" void kernel_launch(void* const* d_in, const int* in_sizes, int n_in,
                              void* d_out, int out_size) {
    const float* x    = (const float*)d_in[0];
    const float* te   = (const float*)d_in[1];
    const int*   mask = (const int*)  d_in[2];
    const float* Wq   = (const float*)d_in[3];
    const float* bq   = (const float*)d_in[4];
    const float* Wk   = (const float*)d_in[5];
    const float* bk   = (const float*)d_in[6];
    const float* Wv   = (const float*)d_in[7];
    const float* bv   = (const float*)d_in[8];
    const float* Wo   = (const float*)d_in[9];
    const float* bo   = (const float*)d_in[10];
    const float* Wt   = (const float*)d_in[11];
    const float* bt   = (const float*)d_in[12];
    float* out = (float*)d_out;

    (void)in_sizes; (void)n_in; (void)out_size;

    cudaFuncSetAttribute(attn_tc_kernel,
                         cudaFuncAttributeMaxDynamicSharedMemorySize,
                         ATTN_SMEM_BYTES);

    preround_kernel<<<dim3(256, 5), 256>>>(x, Wq, Wk, Wv, Wo);
    task_bias_kernel<<<1, 64>>>(te, Wt, bt);
    qkv_gemm_tc_kernel<<<dim3(Dn / 128, Mn / 128, 3), 256>>>(bq, bk, bv);
    attn_tc_kernel<<<dim3(Sn / 128, Hn, Bn), 256, ATTN_SMEM_BYTES>>>(mask);
    out_gemm_tc_kernel<<<dim3(Dn / 128, Mn / 128, 1), 256>>>(bo, out);
}